// round 11
// baseline (speedup 1.0000x reference)
#include <cuda_runtime.h>
#include <cstdint>

#define BB 64
#define TT 2000
#define LLEN 400
#define MMEL 80
#define EPSF 1e-8f
#define LN2 0.6931471805599453

#define NBLOCKS 1180            // 1180*256 = 302080 = 20*15104 (mod-20 trick)
#define NTHREADS 256
#define TOTTHREADS (NBLOCKS * NTHREADS)
#define DBT 15104               // row stride for mel = TOTTHREADS/20
#define DB  7
#define DT  1104

#define NWARPS (NBLOCKS * (NTHREADS / 32))   // 9440
#define ADB 4                   // NWARPS / TT
#define ADT 1440                // NWARPS % TT

__device__ double g_acc[5];     // 0:|mo-tgt| 1:|post-tgt| 2:gate 3:kl2 4:ent2
__device__ unsigned int g_done;

__device__ __forceinline__ float warp_sum(float v) {
#pragma unroll
    for (int o = 16; o > 0; o >>= 1) v += __shfl_xor_sync(0xffffffffu, v, o);
    return v;
}
__device__ __forceinline__ int warp_sum_i(int v) {
#pragma unroll
    for (int o = 16; o > 0; o >>= 1) v += __shfl_xor_sync(0xffffffffu, v, o);
    return v;
}
// Two warp reductions with interleaved shuffles: the two 26-cyc SHFL latency
// chains overlap instead of serializing.
__device__ __forceinline__ void warp_sum2(float& a, float& b) {
#pragma unroll
    for (int o = 16; o > 0; o >>= 1) {
        float ta = __shfl_xor_sync(0xffffffffu, a, o);
        float tb = __shfl_xor_sync(0xffffffffu, b, o);
        a += ta;
        b += tb;
    }
}
__device__ __forceinline__ float ex2_approx(float x) {
    float r;
    asm("ex2.approx.f32 %0, %1;" : "=f"(r) : "f"(x));
    return r;
}

// entropy (log2 space) for one float4; a==1.0 contributes exactly 0.
__device__ __forceinline__ void ent4(float4 v, float& ent2) {
    float a0 = fmaxf(v.x, EPSF), a1 = fmaxf(v.y, EPSF);
    float a2 = fmaxf(v.z, EPSF), a3 = fmaxf(v.w, EPSF);
    ent2 -= a0 * __log2f(a0);
    ent2 -= a1 * __log2f(a1);
    ent2 -= a2 * __log2f(a2);
    ent2 -= a3 * __log2f(a3);
}

// ---------------- mel L1 + gate BCE ----------------------------------------
__device__ __forceinline__ void do_melgate(
    const float* __restrict__ post, const float* __restrict__ mo,
    const float* __restrict__ tgt,  const float* __restrict__ gate_out,
    const float* __restrict__ gate_tgt, const int* __restrict__ s_mlen,
    int tid, float& s1, float& s2, float& sg) {
    const float4* p4 = (const float4*)post;
    const float4* o4 = (const float4*)mo;
    const float4* t4 = (const float4*)tgt;

    int bt   = tid / 20;
    int part = tid - bt * 20;
    int b    = bt / TT;
    int t    = bt - b * TT;
    size_t idx = (size_t)bt * 20 + part;

    while (bt < BB * TT) {
        if (t < s_mlen[b]) {
            float4 a = o4[idx], c = t4[idx], p = p4[idx];
            s1 += fabsf(a.x - c.x) + fabsf(a.y - c.y) +
                  fabsf(a.z - c.z) + fabsf(a.w - c.w);
            s2 += fabsf(p.x - c.x) + fabsf(p.y - c.y) +
                  fabsf(p.z - c.z) + fabsf(p.w - c.w);
        }
        bt  += DBT;
        idx += TOTTHREADS;
        t   += DT; b += DB;
        if (t >= TT) { t -= TT; b += 1; }
    }
    for (int i = tid; i < BB * TT; i += TOTTHREADS) {
        float x = gate_out[i];
        float z = gate_tgt[i];
        sg += fmaxf(x, 0.f) - x * z + __logf(1.f + __expf(-fabsf(x)));
    }
}

// ---------------- attn KL + entropy ----------------------------------------
__device__ __forceinline__ void do_attn(
    const float* __restrict__ attn, const int* __restrict__ s_tlen,
    const float* __restrict__ s_c, const int* __restrict__ s_w,
    int gwarp, int lane, float& kl2_acc, float& ent2_acc) {

    int r = gwarp;
    int b = r / TT;
    int t = r - b * TT;

    const float4 one4 = make_float4(1.f, 1.f, 1.f, 1.f);

    while (r < BB * TT) {
        const int   Lb = s_tlen[b];
        const float c  = s_c[b];
        const int   w  = s_w[b];

        int e = t * Lb / TT;
        if (e > Lb - 1) e = Lb - 1;
        float ef = (float)e;

        // window: only the UPPER bound (validity at Lb / +6σ tail) is hard;
        // sub-window elements included below have g < 2e-9 — negligible.
        int lo4 = e - w; if (lo4 < 0) lo4 = 0;
        lo4 >>= 2;
        int hi  = e + w + 1; if (hi > Lb) hi = Lb;
        int hi4 = (hi + 3) >> 2;

        const float4* row4 = (const float4*)(attn + (size_t)r * LLEN);

        // --- entropy: branch-free, batched loads (MLP=4) ---
        float4 v0 = __ldg(row4 + lane);
        float4 v1 = __ldg(row4 + lane + 32);
        float4 v2 = __ldg(row4 + lane + 64);
        float4 v3 = (lane < 4) ? __ldg(row4 + 96 + lane) : one4;
        ent4(v0, ent2_acc); ent4(v1, ent2_acc);
        ent4(v2, ent2_acc); ent4(v3, ent2_acc);

        // --- Gaussian window (~31 float4s; L1 re-hit), 1 predicate/elem ---
        float S = 0.f, E12 = 0.f;
        for (int q = lo4 + lane; q < hi4; q += 32) {
            float4 av = __ldg(row4 + q);
            int l0 = q * 4;
#pragma unroll
            for (int j = 0; j < 4; j++) {
                float a = (j == 0) ? av.x : (j == 1) ? av.y : (j == 2) ? av.z : av.w;
                int l = l0 + j;
                if (l < hi) {
                    float d   = (float)l - ef;
                    float y   = -c * d * d;          // lg2(g)
                    float g   = ex2_approx(y);
                    float la2 = __log2f(fmaxf(a, EPSF));
                    S   += g;
                    E12 += g * (y - la2);
                }
            }
        }
        warp_sum2(S, E12);
        if (lane == 0) {
            float Sp = S + EPSF;
            kl2_acc += E12 / Sp - (S / Sp) * __log2f(Sp);
        }

        r += NWARPS;
        t += ADT; b += ADB;
        if (t >= TT) { t -= TT; b += 1; }
    }
}

__global__ void __launch_bounds__(NTHREADS, 8)
k_fused(const float* __restrict__ post,
        const float* __restrict__ mo,
        const float* __restrict__ gate_out,
        const float* __restrict__ attn,
        const float* __restrict__ tgt,
        const float* __restrict__ gate_tgt,
        const int*   __restrict__ mel_len,
        const int*   __restrict__ text_len,
        float* __restrict__ out) {
    __shared__ int   s_mlen[BB];
    __shared__ int   s_tlen[BB];
    __shared__ float s_c[BB];       // 0.5*log2e / sigma^2
    __shared__ int   s_w[BB];       // 6*sigma
    if (threadIdx.x < BB) {
        int Lb = text_len[threadIdx.x];
        s_mlen[threadIdx.x] = mel_len[threadIdx.x];
        s_tlen[threadIdx.x] = Lb;
        float sigma = fminf(fmaxf((float)Lb * 0.05f, 3.0f), 10.0f);
        s_c[threadIdx.x] = 0.7213475204444817f / (sigma * sigma);
        s_w[threadIdx.x] = (int)(6.0f * sigma) + 1;
    }
    __syncthreads();

    const int tid   = blockIdx.x * NTHREADS + threadIdx.x;
    const int lane  = threadIdx.x & 31;
    const int wid   = threadIdx.x >> 5;
    const int gwarp = blockIdx.x * (NTHREADS / 32) + wid;

    float s1 = 0.f, s2 = 0.f, sg = 0.f, kl2 = 0.f, ent2 = 0.f;

    // Phase interleave: half the blocks run attn first, half mel first, so
    // DRAM-heavy and MUFU/issue-heavy work is co-resident on every SM.
    if (blockIdx.x & 1) {
        do_attn(attn, s_tlen, s_c, s_w, gwarp, lane, kl2, ent2);
        do_melgate(post, mo, tgt, gate_out, gate_tgt, s_mlen, tid, s1, s2, sg);
    } else {
        do_melgate(post, mo, tgt, gate_out, gate_tgt, s_mlen, tid, s1, s2, sg);
        do_attn(attn, s_tlen, s_c, s_w, gwarp, lane, kl2, ent2);
    }

    // ---------------- block reduce + global accumulate ----------------------
    __shared__ float red[5][NTHREADS / 32];
    warp_sum2(s1, s2);
    warp_sum2(sg, ent2);
    kl2 = warp_sum(kl2);                 // nonzero only in lane 0 already
    if (lane == 0) {
        red[0][wid] = s1; red[1][wid] = s2; red[2][wid] = sg;
        red[3][wid] = kl2; red[4][wid] = ent2;
    }
    __syncthreads();
    if (threadIdx.x == 0) {
        float p0 = 0.f, p1 = 0.f, p2 = 0.f, p3 = 0.f, p4 = 0.f;
        for (int i = 0; i < NTHREADS / 32; i++) {
            p0 += red[0][i]; p1 += red[1][i]; p2 += red[2][i];
            p3 += red[3][i]; p4 += red[4][i];
        }
        atomicAdd(&g_acc[0], (double)p0);
        atomicAdd(&g_acc[1], (double)p1);
        atomicAdd(&g_acc[2], (double)p2);
        atomicAdd(&g_acc[3], (double)p3);
        atomicAdd(&g_acc[4], (double)p4);
    }

    // ---------------- last block: finalize + reset --------------------------
    __shared__ bool is_last;
    __threadfence();
    if (threadIdx.x == 0) {
        unsigned v = atomicAdd(&g_done, 1u);
        is_last = (v == (unsigned)(NBLOCKS - 1));
    }
    __syncthreads();

    if (is_last && threadIdx.x < 32) {
        int s = s_mlen[threadIdx.x] + s_mlen[threadIdx.x + 32];
        s = warp_sum_i(s);
        if (threadIdx.x == 0) {
            double n_valid  = (double)s * (double)MMEL;
            double mel_loss = (g_acc[0] + g_acc[1]) / n_valid;
            double gate     = g_acc[2] / (double)(BB * TT);
            double kl       = LN2 * g_acc[3] / (double)BB / (double)TT;
            if (kl > 150.0) kl = 150.0;
            double ent   = LN2 * g_acc[4] / (double)(BB * TT);
            double ratio = ent / 3.5; if (ratio < 0.0) ratio = 0.0;
            double wgt   = (ent <= 3.5) ? fmax(0.2, ratio) : 1.0;
            out[0] = (float)(mel_loss + gate + wgt * kl);
            out[1] = (float)mel_loss;
            out[2] = (float)gate;
            out[3] = (float)kl;
            g_acc[0] = 0.0; g_acc[1] = 0.0; g_acc[2] = 0.0;
            g_acc[3] = 0.0; g_acc[4] = 0.0;
            __threadfence();
            g_done = 0u;
        }
    }
}

extern "C" void kernel_launch(void* const* d_in, const int* in_sizes, int n_in,
                              void* d_out, int out_size) {
    const float* post     = (const float*)d_in[0];
    const float* mo       = (const float*)d_in[1];
    const float* gate_out = (const float*)d_in[2];
    const float* attn     = (const float*)d_in[3];
    const float* tgt      = (const float*)d_in[4];
    const float* gate_tgt = (const float*)d_in[5];
    const int*   mel_len  = (const int*)  d_in[6];
    const int*   text_len = (const int*)  d_in[7];
    float* out = (float*)d_out;

    k_fused<<<NBLOCKS, NTHREADS>>>(post, mo, gate_out, attn, tgt, gate_tgt,
                                   mel_len, text_len, out);
}

// round 13
// speedup vs baseline: 1.0443x; 1.0443x over previous
#include <cuda_runtime.h>
#include <cstdint>

#define BB 64
#define TT 2000
#define LLEN 400
#define MMEL 80
#define EPSF 1e-8f
#define LN2 0.6931471805599453

#define NBLOCKS 1180            // 1180*256 = 302080 = 20*15104 (mod-20 trick)
#define NTHREADS 256
#define TOTTHREADS (NBLOCKS * NTHREADS)
#define DBT 15104               // row stride for mel = TOTTHREADS/20
#define DB  7
#define DT  1104

#define NWARPS (NBLOCKS * (NTHREADS / 32))   // 9440
#define ADB 4                   // NWARPS / TT
#define ADT 1440                // NWARPS % TT

__device__ double g_acc[5];     // 0:|mo-tgt| 1:|post-tgt| 2:gate 3:kl2 4:ent2
__device__ unsigned int g_done;

__device__ __forceinline__ float warp_sum(float v) {
#pragma unroll
    for (int o = 16; o > 0; o >>= 1) v += __shfl_xor_sync(0xffffffffu, v, o);
    return v;
}
__device__ __forceinline__ int warp_sum_i(int v) {
#pragma unroll
    for (int o = 16; o > 0; o >>= 1) v += __shfl_xor_sync(0xffffffffu, v, o);
    return v;
}
// Two warp reductions with interleaved shuffles: the two 26-cyc SHFL latency
// chains overlap instead of serializing.
__device__ __forceinline__ void warp_sum2(float& a, float& b) {
#pragma unroll
    for (int o = 16; o > 0; o >>= 1) {
        float ta = __shfl_xor_sync(0xffffffffu, a, o);
        float tb = __shfl_xor_sync(0xffffffffu, b, o);
        a += ta;
        b += tb;
    }
}
__device__ __forceinline__ float ex2_approx(float x) {
    float r;
    asm("ex2.approx.f32 %0, %1;" : "=f"(r) : "f"(x));
    return r;
}

// entropy (log2 space) for one float4; a==1.0 contributes exactly 0.
__device__ __forceinline__ void ent4(float4 v, float& ent2) {
    float a0 = fmaxf(v.x, EPSF), a1 = fmaxf(v.y, EPSF);
    float a2 = fmaxf(v.z, EPSF), a3 = fmaxf(v.w, EPSF);
    ent2 -= a0 * __log2f(a0);
    ent2 -= a1 * __log2f(a1);
    ent2 -= a2 * __log2f(a2);
    ent2 -= a3 * __log2f(a3);
}

// ---------------- mel L1 + gate BCE ----------------------------------------
__device__ __forceinline__ void do_melgate(
    const float* __restrict__ post, const float* __restrict__ mo,
    const float* __restrict__ tgt,  const float* __restrict__ gate_out,
    const float* __restrict__ gate_tgt, const int* __restrict__ s_mlen,
    int tid, float& s1, float& s2, float& sg) {
    const float4* p4 = (const float4*)post;
    const float4* o4 = (const float4*)mo;
    const float4* t4 = (const float4*)tgt;

    int bt   = tid / 20;
    int part = tid - bt * 20;
    int b    = bt / TT;
    int t    = bt - b * TT;
    size_t idx = (size_t)bt * 20 + part;

    while (bt < BB * TT) {
        if (t < s_mlen[b]) {
            float4 a = o4[idx], c = t4[idx], p = p4[idx];
            s1 += fabsf(a.x - c.x) + fabsf(a.y - c.y) +
                  fabsf(a.z - c.z) + fabsf(a.w - c.w);
            s2 += fabsf(p.x - c.x) + fabsf(p.y - c.y) +
                  fabsf(p.z - c.z) + fabsf(p.w - c.w);
        }
        bt  += DBT;
        idx += TOTTHREADS;
        t   += DT; b += DB;
        if (t >= TT) { t -= TT; b += 1; }
    }
    for (int i = tid; i < BB * TT; i += TOTTHREADS) {
        float x = gate_out[i];
        float z = gate_tgt[i];
        sg += fmaxf(x, 0.f) - x * z + __logf(1.f + __expf(-fabsf(x)));
    }
}

// ---------------- attn KL + entropy ----------------------------------------
__device__ __forceinline__ void do_attn(
    const float* __restrict__ attn, const int* __restrict__ s_tlen,
    const float* __restrict__ s_c, const int* __restrict__ s_w,
    int gwarp, int lane, float& kl2_acc, float& ent2_acc) {

    int r = gwarp;
    int b = r / TT;
    int t = r - b * TT;

    const float4 one4 = make_float4(1.f, 1.f, 1.f, 1.f);

    while (r < BB * TT) {
        const int   Lb = s_tlen[b];
        const float c  = s_c[b];
        const int   w  = s_w[b];

        int e = t * Lb / TT;
        if (e > Lb - 1) e = Lb - 1;
        float ef = (float)e;

        // window: only the UPPER bound (validity at Lb / +6σ tail) is hard;
        // sub-window elements included below have g < 2e-9 — negligible.
        int lo4 = e - w; if (lo4 < 0) lo4 = 0;
        lo4 >>= 2;
        int hi  = e + w + 1; if (hi > Lb) hi = Lb;
        int hi4 = (hi + 3) >> 2;

        const float4* row4 = (const float4*)(attn + (size_t)r * LLEN);

        // --- entropy: branch-free, batched loads (MLP=4) ---
        float4 v0 = __ldg(row4 + lane);
        float4 v1 = __ldg(row4 + lane + 32);
        float4 v2 = __ldg(row4 + lane + 64);
        float4 v3 = (lane < 4) ? __ldg(row4 + 96 + lane) : one4;
        ent4(v0, ent2_acc); ent4(v1, ent2_acc);
        ent4(v2, ent2_acc); ent4(v3, ent2_acc);

        // --- Gaussian window (~31 float4s; L1 re-hit), 1 predicate/elem ---
        float S = 0.f, E12 = 0.f;
        for (int q = lo4 + lane; q < hi4; q += 32) {
            float4 av = __ldg(row4 + q);
            int l0 = q * 4;
#pragma unroll
            for (int j = 0; j < 4; j++) {
                float a = (j == 0) ? av.x : (j == 1) ? av.y : (j == 2) ? av.z : av.w;
                int l = l0 + j;
                if (l < hi) {
                    float d   = (float)l - ef;
                    float y   = -c * d * d;          // lg2(g)
                    float g   = ex2_approx(y);
                    float la2 = __log2f(fmaxf(a, EPSF));
                    S   += g;
                    E12 += g * (y - la2);
                }
            }
        }
        warp_sum2(S, E12);
        if (lane == 0) {
            float Sp = S + EPSF;
            kl2_acc += E12 / Sp - (S / Sp) * __log2f(Sp);
        }

        r += NWARPS;
        t += ADT; b += ADB;
        if (t >= TT) { t -= TT; b += 1; }
    }
}

__global__ void __launch_bounds__(NTHREADS, 6)   // 42-reg budget: no spills
k_fused(const float* __restrict__ post,
        const float* __restrict__ mo,
        const float* __restrict__ gate_out,
        const float* __restrict__ attn,
        const float* __restrict__ tgt,
        const float* __restrict__ gate_tgt,
        const int*   __restrict__ mel_len,
        const int*   __restrict__ text_len,
        float* __restrict__ out) {
    __shared__ int   s_mlen[BB];
    __shared__ int   s_tlen[BB];
    __shared__ float s_c[BB];       // 0.5*log2e / sigma^2
    __shared__ int   s_w[BB];       // 6*sigma
    if (threadIdx.x < BB) {
        int Lb = text_len[threadIdx.x];
        s_mlen[threadIdx.x] = mel_len[threadIdx.x];
        s_tlen[threadIdx.x] = Lb;
        float sigma = fminf(fmaxf((float)Lb * 0.05f, 3.0f), 10.0f);
        s_c[threadIdx.x] = 0.7213475204444817f / (sigma * sigma);
        s_w[threadIdx.x] = (int)(6.0f * sigma) + 1;
    }
    __syncthreads();

    const int tid   = blockIdx.x * NTHREADS + threadIdx.x;
    const int lane  = threadIdx.x & 31;
    const int wid   = threadIdx.x >> 5;
    const int gwarp = blockIdx.x * (NTHREADS / 32) + wid;

    float s1 = 0.f, s2 = 0.f, sg = 0.f, kl2 = 0.f, ent2 = 0.f;

    // Phase interleave: half the blocks run attn first, half mel first, so
    // DRAM-heavy and MUFU/issue-heavy work is co-resident on every SM.
    if (blockIdx.x & 1) {
        do_attn(attn, s_tlen, s_c, s_w, gwarp, lane, kl2, ent2);
        do_melgate(post, mo, tgt, gate_out, gate_tgt, s_mlen, tid, s1, s2, sg);
    } else {
        do_melgate(post, mo, tgt, gate_out, gate_tgt, s_mlen, tid, s1, s2, sg);
        do_attn(attn, s_tlen, s_c, s_w, gwarp, lane, kl2, ent2);
    }

    // ---------------- block reduce + global accumulate ----------------------
    __shared__ float red[5][NTHREADS / 32];
    warp_sum2(s1, s2);
    warp_sum2(sg, ent2);
    kl2 = warp_sum(kl2);                 // nonzero only in lane 0 already
    if (lane == 0) {
        red[0][wid] = s1; red[1][wid] = s2; red[2][wid] = sg;
        red[3][wid] = kl2; red[4][wid] = ent2;
    }
    __syncthreads();
    if (threadIdx.x == 0) {
        float p0 = 0.f, p1 = 0.f, p2 = 0.f, p3 = 0.f, p4 = 0.f;
        for (int i = 0; i < NTHREADS / 32; i++) {
            p0 += red[0][i]; p1 += red[1][i]; p2 += red[2][i];
            p3 += red[3][i]; p4 += red[4][i];
        }
        atomicAdd(&g_acc[0], (double)p0);
        atomicAdd(&g_acc[1], (double)p1);
        atomicAdd(&g_acc[2], (double)p2);
        atomicAdd(&g_acc[3], (double)p3);
        atomicAdd(&g_acc[4], (double)p4);
    }

    // ---------------- last block: finalize + reset --------------------------
    __shared__ bool is_last;
    __threadfence();
    if (threadIdx.x == 0) {
        unsigned v = atomicAdd(&g_done, 1u);
        is_last = (v == (unsigned)(NBLOCKS - 1));
    }
    __syncthreads();

    if (is_last && threadIdx.x < 32) {
        int s = s_mlen[threadIdx.x] + s_mlen[threadIdx.x + 32];
        s = warp_sum_i(s);
        if (threadIdx.x == 0) {
            double n_valid  = (double)s * (double)MMEL;
            double mel_loss = (g_acc[0] + g_acc[1]) / n_valid;
            double gate     = g_acc[2] / (double)(BB * TT);
            double kl       = LN2 * g_acc[3] / (double)BB / (double)TT;
            if (kl > 150.0) kl = 150.0;
            double ent   = LN2 * g_acc[4] / (double)(BB * TT);
            double ratio = ent / 3.5; if (ratio < 0.0) ratio = 0.0;
            double wgt   = (ent <= 3.5) ? fmax(0.2, ratio) : 1.0;
            out[0] = (float)(mel_loss + gate + wgt * kl);
            out[1] = (float)mel_loss;
            out[2] = (float)gate;
            out[3] = (float)kl;
            g_acc[0] = 0.0; g_acc[1] = 0.0; g_acc[2] = 0.0;
            g_acc[3] = 0.0; g_acc[4] = 0.0;
            __threadfence();
            g_done = 0u;
        }
    }
}

extern "C" void kernel_launch(void* const* d_in, const int* in_sizes, int n_in,
                              void* d_out, int out_size) {
    const float* post     = (const float*)d_in[0];
    const float* mo       = (const float*)d_in[1];
    const float* gate_out = (const float*)d_in[2];
    const float* attn     = (const float*)d_in[3];
    const float* tgt      = (const float*)d_in[4];
    const float* gate_tgt = (const float*)d_in[5];
    const int*   mel_len  = (const int*)  d_in[6];
    const int*   text_len = (const int*)  d_in[7];
    float* out = (float*)d_out;

    k_fused<<<NBLOCKS, NTHREADS>>>(post, mo, gate_out, attn, tgt, gate_tgt,
                                   mel_len, text_len, out);
}

// round 15
// speedup vs baseline: 1.2963x; 1.2413x over previous
#include <cuda_runtime.h>
#include <cstdint>

#define BB 64
#define TT 2000
#define LLEN 400
#define MMEL 80
#define EPSF 1e-8f
#define LN2 0.6931471805599453

#define NBLOCKS 1180            // 1180*256 = 302080 = 20*15104 (mod-20 trick)
#define NTHREADS 256
#define TOTTHREADS (NBLOCKS * NTHREADS)
#define DBT 15104               // row stride for mel = TOTTHREADS/20
#define DB  7
#define DT  1104

#define NWARPS (NBLOCKS * (NTHREADS / 32))   // 9440
#define ADB 4                   // NWARPS / TT
#define ADT 1440                // NWARPS % TT

__device__ double g_acc[5];     // 0:|mo-tgt| 1:|post-tgt| 2:gate 3:kl2 4:ent2
__device__ unsigned int g_done;

__device__ __forceinline__ float warp_sum(float v) {
#pragma unroll
    for (int o = 16; o > 0; o >>= 1) v += __shfl_xor_sync(0xffffffffu, v, o);
    return v;
}
__device__ __forceinline__ int warp_sum_i(int v) {
#pragma unroll
    for (int o = 16; o > 0; o >>= 1) v += __shfl_xor_sync(0xffffffffu, v, o);
    return v;
}

// Fused per-float4: entropy always; Gaussian KL terms only inside [lo, lo+span)
// reusing the already-computed log2(a). One unsigned range check per element.
__device__ __forceinline__ void fuse4(float4 v, int l0, int lo, int span,
                                      float c, float ef,
                                      float& ent2, float& S, float& E12) {
#pragma unroll
    for (int j = 0; j < 4; j++) {
        float a  = (j == 0) ? v.x : (j == 1) ? v.y : (j == 2) ? v.z : v.w;
        int   l  = l0 + j;
        float as = fmaxf(a, EPSF);
        float la = __log2f(as);
        ent2 -= as * la;
        if ((unsigned)(l - lo) < (unsigned)span) {
            float d = (float)l - ef;
            float y = -c * d * d;          // lg2(g)
            float g = exp2f(y);
            S   += g;
            E12 += g * (y - la);
        }
    }
}

// ---------------- mel L1 + gate BCE ----------------------------------------
__device__ __forceinline__ void do_melgate(
    const float* __restrict__ post, const float* __restrict__ mo,
    const float* __restrict__ tgt,  const float* __restrict__ gate_out,
    const float* __restrict__ gate_tgt, const int* __restrict__ s_mlen,
    int tid, float& s1, float& s2, float& sg) {
    const float4* p4 = (const float4*)post;
    const float4* o4 = (const float4*)mo;
    const float4* t4 = (const float4*)tgt;

    int bt   = tid / 20;
    int part = tid - bt * 20;
    int b    = bt / TT;
    int t    = bt - b * TT;
    size_t idx = (size_t)bt * 20 + part;

    while (bt < BB * TT) {
        if (t < s_mlen[b]) {
            float4 a = o4[idx], c = t4[idx], p = p4[idx];
            s1 += fabsf(a.x - c.x) + fabsf(a.y - c.y) +
                  fabsf(a.z - c.z) + fabsf(a.w - c.w);
            s2 += fabsf(p.x - c.x) + fabsf(p.y - c.y) +
                  fabsf(p.z - c.z) + fabsf(p.w - c.w);
        }
        bt  += DBT;
        idx += TOTTHREADS;
        t   += DT; b += DB;
        if (t >= TT) { t -= TT; b += 1; }
    }
    for (int i = tid; i < BB * TT; i += TOTTHREADS) {
        float x = gate_out[i];
        float z = gate_tgt[i];
        sg += fmaxf(x, 0.f) - x * z + log1pf(__expf(-fabsf(x)));
    }
}

// ---------------- attn KL + entropy (single fused pass) ---------------------
__device__ __forceinline__ void do_attn(
    const float* __restrict__ attn, const int* __restrict__ s_tlen,
    const float* __restrict__ s_c, const int* __restrict__ s_w,
    int gwarp, int lane, float& kl2_acc, float& ent2_acc) {

    int r = gwarp;
    int b = r / TT;
    int t = r - b * TT;

    const float4 one4 = make_float4(1.f, 1.f, 1.f, 1.f);

    while (r < BB * TT) {
        const int   Lb = s_tlen[b];
        const float c  = s_c[b];
        const int   w  = s_w[b];

        int e = t * Lb / TT;
        if (e > Lb - 1) e = Lb - 1;
        float ef = (float)e;

        int lo   = e - w;     if (lo < 0)  lo = 0;
        int hi   = e + w + 1; if (hi > Lb) hi = Lb;
        int span = hi - lo;

        const float4* row4 = (const float4*)(attn + (size_t)r * LLEN);

        // one pass: batched loads (MLP=4), entropy + window from same regs
        float4 v0 = __ldg(row4 + lane);
        float4 v1 = __ldg(row4 + lane + 32);
        float4 v2 = __ldg(row4 + lane + 64);
        float4 v3 = (lane < 4) ? __ldg(row4 + 96 + lane) : one4;
        int l3 = (lane < 4) ? 384 + 4 * lane : lo + LLEN;  // dummy: pred false

        float S = 0.f, E12 = 0.f;
        fuse4(v0,       4 * lane, lo, span, c, ef, ent2_acc, S, E12);
        fuse4(v1, 128 + 4 * lane, lo, span, c, ef, ent2_acc, S, E12);
        fuse4(v2, 256 + 4 * lane, lo, span, c, ef, ent2_acc, S, E12);
        fuse4(v3, l3,             lo, span, c, ef, ent2_acc, S, E12);

        S   = warp_sum(S);
        E12 = warp_sum(E12);
        if (lane == 0) {
            float Sp = S + EPSF;
            kl2_acc += E12 / Sp - (S / Sp) * __log2f(Sp);
        }

        r += NWARPS;
        t += ADT; b += ADB;
        if (t >= TT) { t -= TT; b += 1; }
    }
}

__global__ void k_fused(const float* __restrict__ post,
                        const float* __restrict__ mo,
                        const float* __restrict__ gate_out,
                        const float* __restrict__ attn,
                        const float* __restrict__ tgt,
                        const float* __restrict__ gate_tgt,
                        const int*   __restrict__ mel_len,
                        const int*   __restrict__ text_len,
                        float* __restrict__ out) {
    __shared__ int   s_mlen[BB];
    __shared__ int   s_tlen[BB];
    __shared__ float s_c[BB];       // 0.5*log2e / sigma^2
    __shared__ int   s_w[BB];       // 6*sigma + 1
    if (threadIdx.x < BB) {
        int Lb = text_len[threadIdx.x];
        s_mlen[threadIdx.x] = mel_len[threadIdx.x];
        s_tlen[threadIdx.x] = Lb;
        float sigma = fminf(fmaxf((float)Lb * 0.05f, 3.0f), 10.0f);
        s_c[threadIdx.x] = 0.7213475204444817f / (sigma * sigma);
        s_w[threadIdx.x] = (int)(6.0f * sigma) + 1;
    }
    __syncthreads();

    const int tid   = blockIdx.x * NTHREADS + threadIdx.x;
    const int lane  = threadIdx.x & 31;
    const int wid   = threadIdx.x >> 5;
    const int gwarp = blockIdx.x * (NTHREADS / 32) + wid;

    float s1 = 0.f, s2 = 0.f, sg = 0.f, kl2 = 0.f, ent2 = 0.f;

    // Phase interleave: half the blocks run attn first, half mel first, so
    // DRAM-heavy and MUFU/issue-heavy work is co-resident on every SM.
    if (blockIdx.x & 1) {
        do_attn(attn, s_tlen, s_c, s_w, gwarp, lane, kl2, ent2);
        do_melgate(post, mo, tgt, gate_out, gate_tgt, s_mlen, tid, s1, s2, sg);
    } else {
        do_melgate(post, mo, tgt, gate_out, gate_tgt, s_mlen, tid, s1, s2, sg);
        do_attn(attn, s_tlen, s_c, s_w, gwarp, lane, kl2, ent2);
    }

    // ---------------- block reduce + global accumulate ----------------------
    __shared__ float red[5][NTHREADS / 32];
    s1 = warp_sum(s1); s2 = warp_sum(s2); sg = warp_sum(sg);
    kl2 = warp_sum(kl2);                 // nonzero only in lane 0 already
    ent2 = warp_sum(ent2);
    if (lane == 0) {
        red[0][wid] = s1; red[1][wid] = s2; red[2][wid] = sg;
        red[3][wid] = kl2; red[4][wid] = ent2;
    }
    __syncthreads();
    if (threadIdx.x == 0) {
        float p0 = 0.f, p1 = 0.f, p2 = 0.f, p3 = 0.f, p4 = 0.f;
        for (int i = 0; i < NTHREADS / 32; i++) {
            p0 += red[0][i]; p1 += red[1][i]; p2 += red[2][i];
            p3 += red[3][i]; p4 += red[4][i];
        }
        atomicAdd(&g_acc[0], (double)p0);
        atomicAdd(&g_acc[1], (double)p1);
        atomicAdd(&g_acc[2], (double)p2);
        atomicAdd(&g_acc[3], (double)p3);
        atomicAdd(&g_acc[4], (double)p4);
    }

    // ---------------- last block: finalize + reset --------------------------
    __shared__ bool is_last;
    __threadfence();
    if (threadIdx.x == 0) {
        unsigned v = atomicAdd(&g_done, 1u);
        is_last = (v == (unsigned)(NBLOCKS - 1));
    }
    __syncthreads();

    if (is_last && threadIdx.x < 32) {
        int s = s_mlen[threadIdx.x] + s_mlen[threadIdx.x + 32];
        s = warp_sum_i(s);
        if (threadIdx.x == 0) {
            double n_valid  = (double)s * (double)MMEL;
            double mel_loss = (g_acc[0] + g_acc[1]) / n_valid;
            double gate     = g_acc[2] / (double)(BB * TT);
            double kl       = LN2 * g_acc[3] / (double)BB / (double)TT;
            if (kl > 150.0) kl = 150.0;
            double ent   = LN2 * g_acc[4] / (double)(BB * TT);
            double ratio = ent / 3.5; if (ratio < 0.0) ratio = 0.0;
            double wgt   = (ent <= 3.5) ? fmax(0.2, ratio) : 1.0;
            out[0] = (float)(mel_loss + gate + wgt * kl);
            out[1] = (float)mel_loss;
            out[2] = (float)gate;
            out[3] = (float)kl;
            g_acc[0] = 0.0; g_acc[1] = 0.0; g_acc[2] = 0.0;
            g_acc[3] = 0.0; g_acc[4] = 0.0;
            __threadfence();
            g_done = 0u;
        }
    }
}

extern "C" void kernel_launch(void* const* d_in, const int* in_sizes, int n_in,
                              void* d_out, int out_size) {
    const float* post     = (const float*)d_in[0];
    const float* mo       = (const float*)d_in[1];
    const float* gate_out = (const float*)d_in[2];
    const float* attn     = (const float*)d_in[3];
    const float* tgt      = (const float*)d_in[4];
    const float* gate_tgt = (const float*)d_in[5];
    const int*   mel_len  = (const int*)  d_in[6];
    const int*   text_len = (const int*)  d_in[7];
    float* out = (float*)d_out;

    k_fused<<<NBLOCKS, NTHREADS>>>(post, mo, gate_out, attn, tgt, gate_tgt,
                                   mel_len, text_len, out);
}